// round 12
// baseline (speedup 1.0000x reference)
#include <cuda_runtime.h>
#include <cuda_fp16.h>
#include <cstdint>

// ---------------------------------------------------------------------------
// VQVAE forward on sm_103 (ldmatrix + mma.sync fp16 + cp.async).
//   Warp-specialized tile split: warps 0-3 -> n-tiles 0-7 (z cols 0-63),
//   warps 4-7 -> n-tiles 8-15 (z cols 64-99 + 21 fused dot cols at 104-124).
//   Each warp covers 32 rows (2 m16 blocks) -> B ldsm traffic -35%.
//   A scaled 2^8, B scaled 2^10 fp16 split; z = hh only; dots = hh+lh+hl.
//   x rows 0-63 reg-prefetched; rows 64-127 cp.async'd into next buf's Al
//   region (free), converted in place after the MMA block.
// ---------------------------------------------------------------------------

#define NCODES 21
#define LDIM   100
#define IDIM   1024
#define NPAD   128
#define CTA_M  128
#define KC     64
#define NCHUNK (IDIM / KC)

#define ASCALE 256.0f                 // 2^8
#define BSCALE 1024.0f                // 2^10
#define INVS   3.814697265625e-06f    // 2^-18

__device__ __half g_Bh[NPAD * IDIM];
__device__ __half g_Bl[NPAD * IDIM];
__device__ float  g_recon[NCODES * IDIM];
__device__ float  g_ck[NCODES];            // ||c_k||^2 - 2 b.c_k
__device__ double g_loss;

__device__ __forceinline__ uint32_t smem_u32(const void* p) {
    uint32_t a;
    asm("{ .reg .u64 t; cvta.to.shared.u64 t, %1; cvt.u32.u64 %0, t; }"
        : "=r"(a) : "l"(p));
    return a;
}
__device__ __forceinline__ uint32_t pack_f16x2(float a, float b) {
    uint32_t r;   // low 16 = a, high 16 = b
    asm("cvt.rn.f16x2.f32 %0, %1, %2;" : "=r"(r) : "f"(b), "f"(a));
    return r;
}
__device__ __forceinline__ float2 unpack_h2(uint32_t p) {
    __half2 h = *reinterpret_cast<__half2*>(&p);
    return __half22float2(h);
}
__device__ __forceinline__ uint32_t swz(uint32_t o) { return o ^ ((o >> 3) & 0x70u); }

__device__ __forceinline__ void ldsm_x4(uint32_t* r, uint32_t addr) {
    asm volatile("ldmatrix.sync.aligned.m8n8.x4.shared.b16 {%0,%1,%2,%3}, [%4];"
                 : "=r"(r[0]), "=r"(r[1]), "=r"(r[2]), "=r"(r[3]) : "r"(addr));
}
__device__ __forceinline__ void ldsm_x2(uint32_t* r, uint32_t addr) {
    asm volatile("ldmatrix.sync.aligned.m8n8.x2.shared.b16 {%0,%1}, [%2];"
                 : "=r"(r[0]), "=r"(r[1]) : "r"(addr));
}
__device__ __forceinline__ void mma_f16(float* d, const uint32_t* a, const uint32_t* b) {
    asm volatile("mma.sync.aligned.m16n8k16.row.col.f32.f16.f16.f32 "
                 "{%0,%1,%2,%3}, {%4,%5,%6,%7}, {%8,%9}, {%0,%1,%2,%3};"
                 : "+f"(d[0]), "+f"(d[1]), "+f"(d[2]), "+f"(d[3])
                 : "r"(a[0]), "r"(a[1]), "r"(a[2]), "r"(a[3]),
                   "r"(b[0]), "r"(b[1]));
}
#define CP_ASYNC16(dst, src) \
    asm volatile("cp.async.cg.shared.global [%0], [%1], 16;" \
                 :: "r"(dst), "l"(src) : "memory")
#define CP_COMMIT() asm volatile("cp.async.commit_group;" ::: "memory")
#define CP_WAIT0()  asm volatile("cp.async.wait_group 0;" ::: "memory")

// ---------------- smem layout: two 52KB buffers + consts ---------------------
#define BUF_STRIDE 53248
#define OFF_AH   0
#define OFF_AL   16384
#define OFF_BH   32768
#define OFF_BL   49152
#define OFF_BES  106496
#define OFF_CK   107008
#define OFF_ZZ   107136
#define OFF_SIDX 107648
#define OFF_LOSS 108160
#define SMEM_BYTES (108176 + 128)

// ---------------------------------------------------------------------------
// K0: setup — extended B (W_enc rows 0-99, cb@W_enc rows 104-124, rest 0),
//             recon table, ck consts, loss reset
// ---------------------------------------------------------------------------
__global__ void vq_setup_kernel(const float* __restrict__ W_enc,
                                const float* __restrict__ b_enc,
                                const float* __restrict__ codebook,
                                const float* __restrict__ W_dec,
                                const float* __restrict__ b_dec) {
    int g = blockIdx.x * 256 + threadIdx.x;            // 0 .. 131071
    {
        int n = g >> 10, k = g & 1023;
        float w = 0.f;
        if (n < LDIM) {
            w = W_enc[n * IDIM + k];
        } else if (n >= 104 && n < 104 + NCODES) {
            const float* cb = codebook + (n - 104) * LDIM;
#pragma unroll 20
            for (int j = 0; j < LDIM; ++j) w += cb[j] * W_enc[j * IDIM + k];
        }
        float ws = w * BSCALE;
        __half h = __float2half_rn(ws);
        g_Bh[g] = h;
        g_Bl[g] = __float2half_rn(ws - __half2float(h));
    }
    if (g < NCODES * IDIM) {
        int k = g >> 10, d = g & 1023;
        const float4* c4 = (const float4*)(codebook + k * LDIM);
        const float4* w4 = (const float4*)(W_dec + (size_t)d * LDIM);
        float s = b_dec[d];
#pragma unroll
        for (int j = 0; j < LDIM / 4; ++j) {
            float4 a = c4[j], b = w4[j];
            s += a.x * b.x + a.y * b.y + a.z * b.z + a.w * b.w;
        }
        g_recon[g] = s;
    }
    if (g < NCODES) {
        const float* c = codebook + g * LDIM;
        float cn = 0.f, bk = 0.f;
#pragma unroll 10
        for (int j = 0; j < LDIM; ++j) { cn += c[j] * c[j]; bk += b_enc[j] * c[j]; }
        g_ck[g] = cn - 2.f * bk;
    }
    if (g == 0) g_loss = 0.0;
}

// ---------------------------------------------------------------------------
// K1: main
// ---------------------------------------------------------------------------
extern __shared__ __align__(16) char dsm_raw[];

__global__ __launch_bounds__(256, 2)
void vq_main_kernel(const float* __restrict__ x,
                    const float* __restrict__ b_enc,
                    float* __restrict__ out_recon,
                    float* __restrict__ out_idx) {
    const int t = threadIdx.x;
    const int w = t >> 5, L = t & 31;
    const int row0 = blockIdx.x * CTA_M;

    uint32_t raw  = smem_u32(dsm_raw);
    uint32_t base = (raw + 127u) & ~127u;
    char* sm = dsm_raw + (base - raw);

    float* bes   = (float*)(sm + OFF_BES);
    float* cks   = (float*)(sm + OFF_CK);
    float* zzb   = (float*)(sm + OFF_ZZ);
    int*   sidx  = (int*)  (sm + OFF_SIDX);
    float* sloss = (float*)(sm + OFF_LOSS);

    if (t < LDIM)   bes[t] = b_enc[t];
    if (t < NCODES) cks[t] = g_ck[t];
    if (t == 0)     *sloss = 0.f;

    const bool isA = (w < 4);          // warps 0-3: tiles 0-7; 4-7: tiles 8-15
    const int  wl  = w & 3;            // row-group owner: rows wl*32 .. +31

    float acc[2][8][4];                // [m-block][local tile][frag]
#pragma unroll
    for (int b = 0; b < 2; ++b)
#pragma unroll
        for (int j = 0; j < 8; ++j)
#pragma unroll
            for (int e = 0; e < 4; ++e) acc[b][j][e] = 0.f;

    const uint32_t mask  = (uint32_t)(L & 7) << 4;
    const uint32_t lowA0 = ((uint32_t)(L & 7) << 7) + ((uint32_t)(L >> 4) << 4);
    const uint32_t lowB4 = ((uint32_t)(L & 7) << 7) + ((uint32_t)((L >> 3) & 1) << 4)
                         + ((uint32_t)(L >> 4) << 10);
    const uint32_t aRow01 = ((uint32_t)(wl * 4 + ((L >> 3) & 1))) << 10;

    // conversion coords: colf = float column within the 64-col chunk
    const int colf = (t & 15) * 4;

    // ---- staging lambdas ----------------------------------------------------
    auto stageB = [&](int ch, int buf) {
        const int kc = ch * KC;
        uint32_t bOff = base + buf * BUF_STRIDE;
        int n8 = t >> 3, k8 = (t & 7) * 8;
#pragma unroll
        for (int it = 0; it < 4; ++it) {
            int n = it * 32 + n8;
            uint32_t dst = bOff + OFF_BH + swz((uint32_t)(n * 128 + k8 * 2));
            CP_ASYNC16(dst, (const void*)(g_Bh + (size_t)n * IDIM + kc + k8));
        }
        {
            uint32_t dst = bOff + OFF_BL + swz((uint32_t)(n8 * 128 + k8 * 2));
            CP_ASYNC16(dst, (const void*)(g_Bl + (size_t)(96 + n8) * IDIM + kc + k8));
        }
    };
    auto stageRawX = [&](int ch, int buf) {      // rows 64..127 -> buf's AL region
        const int kc = ch * KC;
        uint32_t dstBase = base + buf * BUF_STRIDE + OFF_AL;
        int rsub = (t >> 4) - 8;                 // 0..7 for t in [128,256)
#pragma unroll
        for (int it = 0; it < 8; ++it) {
            int row = 64 + it * 8 + rsub;
            uint32_t dst = dstBase + (uint32_t)((row - 64) * 256 + (t & 15) * 16);
            CP_ASYNC16(dst, (const void*)(x + (size_t)(row0 + row) * IDIM + kc + colf));
        }
    };
    auto loadXv = [&](int ch, float4* xv) {      // rows 0..63, group A threads
        const float* xp = x + ch * KC + colf;
#pragma unroll
        for (int it = 0; it < 8; ++it)
            xv[it] = *(const float4*)(xp + (size_t)(row0 + it * 8 + (t >> 4)) * IDIM);
    };
    auto cvstore = [&](float4 v, int row, char* Ah, char* Al) {
        float sx = v.x * ASCALE, sy = v.y * ASCALE;
        float sz = v.z * ASCALE, sw = v.w * ASCALE;
        uint32_t h01 = pack_f16x2(sx, sy);
        uint32_t h23 = pack_f16x2(sz, sw);
        float2 b01 = unpack_h2(h01), b23 = unpack_h2(h23);
        uint32_t l01 = pack_f16x2(sx - b01.x, sy - b01.y);
        uint32_t l23 = pack_f16x2(sz - b23.x, sw - b23.y);
        uint32_t off = swz((uint32_t)(row * 128 + colf * 2));
        *(uint2*)(Ah + off) = make_uint2(h01, h23);
        *(uint2*)(Al + off) = make_uint2(l01, l23);
    };

    // ---- prologue: chunk 0 --------------------------------------------------
    float4 xv[8];
    if (isA) loadXv(0, xv);
    else     stageRawX(0, 0);
    stageB(0, 0);
    CP_COMMIT();
    CP_WAIT0();
    {
        float4 rv[8];
        if (!isA) {
            const char* rawp = sm + 0 * BUF_STRIDE + OFF_AL;
            int rsub = (t >> 4) - 8;
#pragma unroll
            for (int it = 0; it < 8; ++it)
                rv[it] = *(const float4*)(rawp + (it * 8 + rsub) * 256 + (t & 15) * 16);
        }
        __syncthreads();
        char* Ah = sm + OFF_AH;  char* Al = sm + OFF_AL;
        if (isA) {
#pragma unroll
            for (int it = 0; it < 8; ++it)
                cvstore(xv[it], it * 8 + (t >> 4), Ah, Al);
        } else {
#pragma unroll
            for (int it = 0; it < 8; ++it)
                cvstore(rv[it], 56 + it * 8 + (t >> 4), Ah, Al);
        }
    }
    __syncthreads();

    // ---- main loop ------------------------------------------------------------
    for (int ch = 0; ch < NCHUNK; ++ch) {
        const int buf  = ch & 1;
        const int nbuf = buf ^ 1;
        const uint32_t bufAdd = (uint32_t)(buf * BUF_STRIDE);
        const uint32_t AhB = base + bufAdd + OFF_AH + aRow01;
        const uint32_t AlB = base + bufAdd + OFF_AL + aRow01;
        const uint32_t BhB = base + bufAdd + OFF_BH;
        const uint32_t BlB = base + bufAdd + OFF_BL - (12 << 10);

        const bool more = (ch + 1 < NCHUNK);
        if (more) {
            if (isA) loadXv(ch + 1, xv);
            else     stageRawX(ch + 1, nbuf);
            stageB(ch + 1, nbuf);
            CP_COMMIT();
        }

#pragma unroll
        for (int ks = 0; ks < 4; ++ks) {
            const uint32_t aoff = (lowA0 + (ks << 5)) ^ mask;
            const uint32_t boff = (lowB4 + (ks << 5)) ^ mask;
            if (isA) {
                uint32_t ah0[4], ah1[4];
                ldsm_x4(ah0, AhB + aoff);
                ldsm_x4(ah1, AhB + (2 << 10) + aoff);
#pragma unroll
                for (int jp = 0; jp < 8; jp += 2) {
                    uint32_t bh[4];
                    ldsm_x4(bh, BhB + boff + (jp << 10));
                    mma_f16(acc[0][jp],     ah0, bh);
                    mma_f16(acc[0][jp + 1], ah0, bh + 2);
                    mma_f16(acc[1][jp],     ah1, bh);
                    mma_f16(acc[1][jp + 1], ah1, bh + 2);
                }
            } else {
                uint32_t ah0[4], ah1[4], al0[4], al1[4];
                ldsm_x4(ah0, AhB + aoff);
                ldsm_x4(ah1, AhB + (2 << 10) + aoff);
                ldsm_x4(al0, AlB + aoff);
                ldsm_x4(al1, AlB + (2 << 10) + aoff);
                // z tiles 8-11 (1 product)
#pragma unroll
                for (int jp = 8; jp < 12; jp += 2) {
                    uint32_t bh[4];
                    ldsm_x4(bh, BhB + boff + (jp << 10));
                    mma_f16(acc[0][jp - 8], ah0, bh);
                    mma_f16(acc[0][jp - 7], ah0, bh + 2);
                    mma_f16(acc[1][jp - 8], ah1, bh);
                    mma_f16(acc[1][jp - 7], ah1, bh + 2);
                }
                // z tile 12 (cols 96-103, 1 product)
                {
                    uint32_t b12[2];
                    ldsm_x2(b12, BhB + boff + (12 << 10));
                    mma_f16(acc[0][4], ah0, b12);
                    mma_f16(acc[1][4], ah1, b12);
                }
                // dot tiles 13,14 (3 products)
                {
                    uint32_t bh[4], bl[4];
                    ldsm_x4(bh, BhB + boff + (13 << 10));
                    ldsm_x4(bl, BlB + boff + (13 << 10));
                    mma_f16(acc[0][5], ah0, bh);
                    mma_f16(acc[0][5], al0, bh);
                    mma_f16(acc[0][5], ah0, bl);
                    mma_f16(acc[1][5], ah1, bh);
                    mma_f16(acc[1][5], al1, bh);
                    mma_f16(acc[1][5], ah1, bl);
                    mma_f16(acc[0][6], ah0, bh + 2);
                    mma_f16(acc[0][6], al0, bh + 2);
                    mma_f16(acc[0][6], ah0, bl + 2);
                    mma_f16(acc[1][6], ah1, bh + 2);
                    mma_f16(acc[1][6], al1, bh + 2);
                    mma_f16(acc[1][6], ah1, bl + 2);
                }
                // dot tile 15 (3 products)
                {
                    uint32_t bh[2], bl[2];
                    ldsm_x2(bh, BhB + boff + (15 << 10));
                    ldsm_x2(bl, BlB + boff + (15 << 10));
                    mma_f16(acc[0][7], ah0, bh);
                    mma_f16(acc[0][7], al0, bh);
                    mma_f16(acc[0][7], ah0, bl);
                    mma_f16(acc[1][7], ah1, bh);
                    mma_f16(acc[1][7], al1, bh);
                    mma_f16(acc[1][7], ah1, bl);
                }
            }
        }

        if (more) {
            CP_WAIT0();
            float4 rv[8];
            if (!isA) {
                const char* rawp = sm + nbuf * BUF_STRIDE + OFF_AL;
                int rsub = (t >> 4) - 8;
#pragma unroll
                for (int it = 0; it < 8; ++it)
                    rv[it] = *(const float4*)(rawp + (it * 8 + rsub) * 256 + (t & 15) * 16);
            }
            __syncthreads();        // raw reads done before AL overwritten
            char* Ah = sm + nbuf * BUF_STRIDE + OFF_AH;
            char* Al = sm + nbuf * BUF_STRIDE + OFF_AL;
            if (isA) {
#pragma unroll
                for (int it = 0; it < 8; ++it)
                    cvstore(xv[it], it * 8 + (t >> 4), Ah, Al);
            } else {
#pragma unroll
                for (int it = 0; it < 8; ++it)
                    cvstore(rv[it], 56 + it * 8 + (t >> 4), Ah, Al);
            }
            __syncthreads();        // tiles ready for next chunk
        }
    }

    // ---- epilogue -------------------------------------------------------------
    const int c0 = L & 3, q = L >> 2;
    float zz[2][2] = {{0.f, 0.f}, {0.f, 0.f}};
    float bd[2][2] = {{3.4e38f, 3.4e38f}, {3.4e38f, 3.4e38f}};
    int   bk[2][2] = {{NCODES, NCODES}, {NCODES, NCODES}};

    if (isA) {
#pragma unroll
        for (int j = 0; j < 8; ++j) {
#pragma unroll
            for (int e = 0; e < 2; ++e) {
                int col = 8 * j + 2 * c0 + e;     // 0..63
                float b = bes[col];
                float z;
                z = fmaf(acc[0][j][e],     INVS, b);  zz[0][0] += z * z;
                z = fmaf(acc[0][j][e + 2], INVS, b);  zz[0][1] += z * z;
                z = fmaf(acc[1][j][e],     INVS, b);  zz[1][0] += z * z;
                z = fmaf(acc[1][j][e + 2], INVS, b);  zz[1][1] += z * z;
            }
        }
    } else {
#pragma unroll
        for (int j = 0; j < 5; ++j) {            // tiles 8..12 -> cols 64..103
#pragma unroll
            for (int e = 0; e < 2; ++e) {
                int col = 64 + 8 * j + 2 * c0 + e;
                if (col < LDIM) {
                    float b = bes[col];
                    float z;
                    z = fmaf(acc[0][j][e],     INVS, b);  zz[0][0] += z * z;
                    z = fmaf(acc[0][j][e + 2], INVS, b);  zz[0][1] += z * z;
                    z = fmaf(acc[1][j][e],     INVS, b);  zz[1][0] += z * z;
                    z = fmaf(acc[1][j][e + 2], INVS, b);  zz[1][1] += z * z;
                }
            }
        }
#pragma unroll
        for (int j = 5; j < 8; ++j) {            // tiles 13..15 -> cols 104..127
#pragma unroll
            for (int e = 0; e < 2; ++e) {
                int k = 8 * (j - 5) + 2 * c0 + e;    // col - 104
                if (k < NCODES) {
                    float ckv = cks[k];
                    float s;
                    s = fmaf(acc[0][j][e],     -2.f * INVS, ckv);
                    if (s < bd[0][0]) { bd[0][0] = s; bk[0][0] = k; }
                    s = fmaf(acc[0][j][e + 2], -2.f * INVS, ckv);
                    if (s < bd[0][1]) { bd[0][1] = s; bk[0][1] = k; }
                    s = fmaf(acc[1][j][e],     -2.f * INVS, ckv);
                    if (s < bd[1][0]) { bd[1][0] = s; bk[1][0] = k; }
                    s = fmaf(acc[1][j][e + 2], -2.f * INVS, ckv);
                    if (s < bd[1][1]) { bd[1][1] = s; bk[1][1] = k; }
                }
            }
        }
    }
    // quad reduce: zz sums; bd/bk min (first-min -> smaller k wins ties)
#pragma unroll
    for (int off = 1; off < 4; off <<= 1) {
#pragma unroll
        for (int b = 0; b < 2; ++b)
#pragma unroll
            for (int h = 0; h < 2; ++h) {
                zz[b][h] += __shfl_xor_sync(0xffffffffu, zz[b][h], off);
                float od = __shfl_xor_sync(0xffffffffu, bd[b][h], off);
                int   ok = __shfl_xor_sync(0xffffffffu, bk[b][h], off);
                if (od < bd[b][h] || (od == bd[b][h] && ok < bk[b][h])) {
                    bd[b][h] = od; bk[b][h] = ok;
                }
            }
    }
    if (isA && c0 == 0) {
#pragma unroll
        for (int b = 0; b < 2; ++b)
#pragma unroll
            for (int h = 0; h < 2; ++h)
                zzb[wl * 32 + b * 16 + h * 8 + q] = zz[b][h];
    }
    __syncthreads();
    if (!isA && c0 == 0) {
        float lsum = 0.f;
#pragma unroll
        for (int b = 0; b < 2; ++b)
#pragma unroll
            for (int h = 0; h < 2; ++h) {
                int r = wl * 32 + b * 16 + h * 8 + q;
                lsum += zzb[r] + zz[b][h] + bd[b][h];
                sidx[r] = bk[b][h];
                out_idx[row0 + r] = (float)bk[b][h];
            }
        atomicAdd(sloss, lsum);
    }
    __syncthreads();
    if (t == 0) atomicAdd(&g_loss, (double)*sloss);

    // ---- fused recon gather (table L2-resident)
#pragma unroll 4
    for (int r = 0; r < CTA_M; ++r) {
        int k = sidx[r];
        float4 v = *(const float4*)(g_recon + (size_t)k * IDIM + t * 4);
        *(float4*)(out_recon + (size_t)(row0 + r) * IDIM + t * 4) = v;
    }
}

// ---------------------------------------------------------------------------
// K2: finalize loss
// ---------------------------------------------------------------------------
__global__ void vq_fin_kernel(float* __restrict__ out_loss, int M) {
    out_loss[0] = (float)(1.1 * g_loss / ((double)M * (double)LDIM));
}

extern "C" void kernel_launch(void* const* d_in, const int* in_sizes, int n_in,
                              void* d_out, int out_size) {
    const float* x        = (const float*)d_in[0];
    const float* W_enc    = (const float*)d_in[1];
    const float* b_enc    = (const float*)d_in[2];
    const float* codebook = (const float*)d_in[3];
    const float* W_dec    = (const float*)d_in[4];
    const float* b_dec    = (const float*)d_in[5];
    float* out = (float*)d_out;

    const int M = in_sizes[0] / IDIM;           // 65536
    float* out_recon = out;
    float* out_loss  = out + (size_t)M * IDIM;
    float* out_idx   = out_loss + 1;

    cudaFuncSetAttribute(vq_main_kernel,
                         cudaFuncAttributeMaxDynamicSharedMemorySize, SMEM_BYTES);

    vq_setup_kernel<<<(NPAD * IDIM) / 256, 256>>>(W_enc, b_enc, codebook, W_dec, b_dec);
    vq_main_kernel<<<M / CTA_M, 256, SMEM_BYTES>>>(x, b_enc, out_recon, out_idx);
    vq_fin_kernel<<<1, 1>>>(out_loss, M);
}

// round 13
// speedup vs baseline: 1.1692x; 1.1692x over previous
#include <cuda_runtime.h>
#include <cuda_fp16.h>
#include <cstdint>

// ---------------------------------------------------------------------------
// VQVAE forward on sm_103 (ldmatrix + mma.sync fp16 + cp.async).
//   z_e = x @ W_enc^T + b_enc  via scaled fp16-split HMMA (fp32 accum)
//     A scaled 2^8, B scaled 2^10 -> residuals stay fp16-normal.
//     z tiles   (cols  0..103): 1 product  (hh)           (feeds loss mean only)
//     dot tiles (cols 104..124): 3 products (hh + lh + hl) fp32-level (argmin)
//   double-buffered smem; B staged with cp.async one chunk ahead;
//   x register-prefetched one chunk ahead; one syncthreads per chunk.
//   argmin / loss  : in-register epilogue + quad shfl reduce
//   x_recon        : fused gather from precomputed 21x1024 table, streaming st
// ---------------------------------------------------------------------------

#define NCODES 21
#define LDIM   100
#define IDIM   1024
#define NPAD   128
#define CTA_M  128
#define KC     64
#define NCHUNK (IDIM / KC)
#define NT     16

#define ASCALE 256.0f                 // 2^8
#define BSCALE 1024.0f                // 2^10
#define INVS   3.814697265625e-06f    // 2^-18

__device__ __half g_Bh[NPAD * IDIM];
__device__ __half g_Bl[NPAD * IDIM];
__device__ float  g_recon[NCODES * IDIM];
__device__ float  g_ck[NCODES];            // ||c_k||^2 - 2 b.c_k
__device__ double g_loss;

__device__ __forceinline__ uint32_t smem_u32(const void* p) {
    uint32_t a;
    asm("{ .reg .u64 t; cvta.to.shared.u64 t, %1; cvt.u32.u64 %0, t; }"
        : "=r"(a) : "l"(p));
    return a;
}
__device__ __forceinline__ uint32_t pack_f16x2(float a, float b) {
    uint32_t r;   // low 16 = a, high 16 = b
    asm("cvt.rn.f16x2.f32 %0, %1, %2;" : "=r"(r) : "f"(b), "f"(a));
    return r;
}
__device__ __forceinline__ float2 unpack_h2(uint32_t p) {
    __half2 h = *reinterpret_cast<__half2*>(&p);
    return __half22float2(h);
}
__device__ __forceinline__ uint32_t swz(uint32_t o) { return o ^ ((o >> 3) & 0x70u); }

__device__ __forceinline__ void ldsm_x4(uint32_t* r, uint32_t addr) {
    asm volatile("ldmatrix.sync.aligned.m8n8.x4.shared.b16 {%0,%1,%2,%3}, [%4];"
                 : "=r"(r[0]), "=r"(r[1]), "=r"(r[2]), "=r"(r[3]) : "r"(addr));
}
__device__ __forceinline__ void ldsm_x2(uint32_t* r, uint32_t addr) {
    asm volatile("ldmatrix.sync.aligned.m8n8.x2.shared.b16 {%0,%1}, [%2];"
                 : "=r"(r[0]), "=r"(r[1]) : "r"(addr));
}
__device__ __forceinline__ void mma_f16(float* d, const uint32_t* a, const uint32_t* b) {
    asm volatile("mma.sync.aligned.m16n8k16.row.col.f32.f16.f16.f32 "
                 "{%0,%1,%2,%3}, {%4,%5,%6,%7}, {%8,%9}, {%0,%1,%2,%3};"
                 : "+f"(d[0]), "+f"(d[1]), "+f"(d[2]), "+f"(d[3])
                 : "r"(a[0]), "r"(a[1]), "r"(a[2]), "r"(a[3]),
                   "r"(b[0]), "r"(b[1]));
}
__device__ __forceinline__ void stcs4(float* p, float4 v) {
    asm volatile("st.global.cs.v4.f32 [%0], {%1,%2,%3,%4};"
                 :: "l"(p), "f"(v.x), "f"(v.y), "f"(v.z), "f"(v.w) : "memory");
}
#define CP_ASYNC16(dst, src) \
    asm volatile("cp.async.cg.shared.global [%0], [%1], 16;" \
                 :: "r"(dst), "l"(src) : "memory")
#define CP_COMMIT() asm volatile("cp.async.commit_group;" ::: "memory")
#define CP_WAIT0()  asm volatile("cp.async.wait_group 0;" ::: "memory")

// ---------------- smem layout: two 52KB buffers + consts ---------------------
#define BUF_STRIDE 53248
#define OFF_AH   0
#define OFF_AL   16384
#define OFF_BH   32768
#define OFF_BL   49152          // 32 rows (96..127) -> 4 KB
#define OFF_BES  106496
#define OFF_CK   107008
#define OFF_SIDX 107136
#define OFF_LOSS 107648
#define SMEM_BYTES (107664 + 128)

// ---------------------------------------------------------------------------
// K0: setup — extended B (W_enc rows 0..99, cb@W_enc rows 104..124, rest 0),
//             recon table, ck consts, loss reset
// ---------------------------------------------------------------------------
__global__ void vq_setup_kernel(const float* __restrict__ W_enc,
                                const float* __restrict__ b_enc,
                                const float* __restrict__ codebook,
                                const float* __restrict__ W_dec,
                                const float* __restrict__ b_dec) {
    int g = blockIdx.x * 256 + threadIdx.x;            // 0 .. 131071
    {
        int n = g >> 10, k = g & 1023;
        float w = 0.f;
        if (n < LDIM) {
            w = W_enc[n * IDIM + k];
        } else if (n >= 104 && n < 104 + NCODES) {
            const float* cb = codebook + (n - 104) * LDIM;
#pragma unroll 20
            for (int j = 0; j < LDIM; ++j) w += cb[j] * W_enc[j * IDIM + k];
        }
        float ws = w * BSCALE;
        __half h = __float2half_rn(ws);
        g_Bh[g] = h;
        g_Bl[g] = __float2half_rn(ws - __half2float(h));
    }
    if (g < NCODES * IDIM) {
        int k = g >> 10, d = g & 1023;
        const float4* c4 = (const float4*)(codebook + k * LDIM);
        const float4* w4 = (const float4*)(W_dec + (size_t)d * LDIM);
        float s = b_dec[d];
#pragma unroll
        for (int j = 0; j < LDIM / 4; ++j) {
            float4 a = c4[j], b = w4[j];
            s += a.x * b.x + a.y * b.y + a.z * b.z + a.w * b.w;
        }
        g_recon[g] = s;
    }
    if (g < NCODES) {
        const float* c = codebook + g * LDIM;
        float cn = 0.f, bk = 0.f;
#pragma unroll 10
        for (int j = 0; j < LDIM; ++j) { cn += c[j] * c[j]; bk += b_enc[j] * c[j]; }
        g_ck[g] = cn - 2.f * bk;
    }
    if (g == 0) g_loss = 0.0;
}

// ---------------------------------------------------------------------------
// K1: main — HMMA scaled-fp16-split GEMM + fused argmin/loss/recon
// ---------------------------------------------------------------------------
extern __shared__ __align__(16) char dsm_raw[];

__global__ __launch_bounds__(256, 2)
void vq_main_kernel(const float* __restrict__ x,
                    const float* __restrict__ b_enc,
                    float* __restrict__ out_recon,
                    float* __restrict__ out_idx) {
    const int t = threadIdx.x;
    const int w = t >> 5, L = t & 31;
    const int row0 = blockIdx.x * CTA_M;

    uint32_t raw  = smem_u32(dsm_raw);
    uint32_t base = (raw + 127u) & ~127u;
    char* sm = dsm_raw + (base - raw);

    float* bes   = (float*)(sm + OFF_BES);
    float* cks   = (float*)(sm + OFF_CK);
    int*   sidx  = (int*)  (sm + OFF_SIDX);
    float* sloss = (float*)(sm + OFF_LOSS);

    if (t < LDIM)   bes[t] = b_enc[t];
    if (t < NCODES) cks[t] = g_ck[t];
    if (t == 0)     *sloss = 0.f;

    float acc[NT][4];
#pragma unroll
    for (int j = 0; j < NT; ++j)
#pragma unroll
        for (int e = 0; e < 4; ++e) acc[j][e] = 0.f;

    const uint32_t mask  = (uint32_t)(L & 7) << 4;
    const uint32_t lowA0 = ((uint32_t)(L & 7) << 7) + ((uint32_t)(L >> 4) << 4);
    const uint32_t lowB4 = ((uint32_t)(L & 7) << 7) + ((uint32_t)((L >> 3) & 1) << 4)
                         + ((uint32_t)(L >> 4) << 10);
    const uint32_t aRow  = ((uint32_t)(w * 2 + ((L >> 3) & 1))) << 10;

    // per-thread source coords
    const int xr = (t >> 4);          // row group within 16
    const int xc = (t & 15) * 4;      // k offset (4 floats)

    // staging coords (B)
    const int sb_n  = t >> 3;                 // 0..31
    const int sb_k8 = (t & 7) * 8;

    // ---- helpers as lambdas -------------------------------------------------
    auto stageB = [&](int ch, int buf) {
        const int kc = ch * KC;
        uint32_t bOff = base + buf * BUF_STRIDE;
#pragma unroll
        for (int it = 0; it < 4; ++it) {
            int n = it * 32 + sb_n;
            uint32_t dst = bOff + OFF_BH + swz((uint32_t)(n * 128 + sb_k8 * 2));
            CP_ASYNC16(dst, (const void*)(g_Bh + (size_t)n * IDIM + kc + sb_k8));
        }
        {
            uint32_t dst = bOff + OFF_BL + swz((uint32_t)(sb_n * 128 + sb_k8 * 2));
            CP_ASYNC16(dst, (const void*)(g_Bl + (size_t)(96 + sb_n) * IDIM + kc + sb_k8));
        }
        CP_COMMIT();
    };
    auto convertA = [&](const float4* xv, int buf) {
        char* Ah = sm + buf * BUF_STRIDE + OFF_AH;
        char* Al = sm + buf * BUF_STRIDE + OFF_AL;
#pragma unroll
        for (int it = 0; it < 8; ++it) {
            float4 v = xv[it];
            int row = it * 16 + xr;
            float sx = v.x * ASCALE, sy = v.y * ASCALE;
            float sz = v.z * ASCALE, sw = v.w * ASCALE;
            uint32_t h01 = pack_f16x2(sx, sy);
            uint32_t h23 = pack_f16x2(sz, sw);
            float2 b01 = unpack_h2(h01), b23 = unpack_h2(h23);
            uint32_t l01 = pack_f16x2(sx - b01.x, sy - b01.y);
            uint32_t l23 = pack_f16x2(sz - b23.x, sw - b23.y);
            uint32_t off = swz((uint32_t)(row * 128 + xc * 2));
            *(uint2*)(Ah + off) = make_uint2(h01, h23);
            *(uint2*)(Al + off) = make_uint2(l01, l23);
        }
    };

    // ---- prologue: chunk 0 staged synchronously
    float4 xv[8];
#pragma unroll
    for (int it = 0; it < 8; ++it)
        xv[it] = *(const float4*)(x + (size_t)(row0 + it * 16 + xr) * IDIM + xc);
    stageB(0, 0);
    convertA(xv, 0);
    CP_WAIT0();
    __syncthreads();

    for (int ch = 0; ch < NCHUNK; ++ch) {
        const int buf  = ch & 1;
        const int nbuf = buf ^ 1;
        const uint32_t bufAdd = (uint32_t)(buf * BUF_STRIDE);
        const uint32_t AhB = base + bufAdd + OFF_AH + aRow;
        const uint32_t AlB = base + bufAdd + OFF_AL + aRow;
        const uint32_t BhB = base + bufAdd + OFF_BH;
        const uint32_t BlB = base + bufAdd + OFF_BL - (12 << 10);

        const bool more = (ch + 1 < NCHUNK);
        if (more) {
            // prefetch next x into regs + async-stage next B (hidden by MMAs)
            const float* xn = x + (ch + 1) * KC + xc;
#pragma unroll
            for (int it = 0; it < 8; ++it)
                xv[it] = *(const float4*)(xn + (size_t)(row0 + it * 16 + xr) * IDIM);
            stageB(ch + 1, nbuf);
        }

#pragma unroll
        for (int ks = 0; ks < 4; ++ks) {
            const uint32_t aoff = (lowA0 + (ks << 5)) ^ mask;
            const uint32_t boff = (lowB4 + (ks << 5)) ^ mask;
            uint32_t ah[4], al[4];
            ldsm_x4(ah, AhB + aoff);
            ldsm_x4(al, AlB + aoff);
#pragma unroll
            for (int j = 0; j < 12; j += 2) {       // z tiles 0..11: hh only
                uint32_t bh[4];
                ldsm_x4(bh, BhB + boff + (j << 10));
                mma_f16(acc[j],     ah, bh);
                mma_f16(acc[j + 1], ah, bh + 2);
            }
            {                                       // z tile 12 (cols 96..103): hh
                uint32_t b12[2];
                ldsm_x2(b12, BhB + boff + (12 << 10));
                mma_f16(acc[12], ah, b12);
            }
            {                                       // dot tiles 13,14: hh+lh+hl
                uint32_t bh[4], bl[4];
                ldsm_x4(bh, BhB + boff + (13 << 10));
                ldsm_x4(bl, BlB + boff + (13 << 10));
                mma_f16(acc[13], ah, bh);
                mma_f16(acc[13], al, bh);
                mma_f16(acc[13], ah, bl);
                mma_f16(acc[14], ah, bh + 2);
                mma_f16(acc[14], al, bh + 2);
                mma_f16(acc[14], ah, bl + 2);
            }
            {                                       // dot tile 15: hh+lh+hl
                uint32_t bh[2], bl[2];
                ldsm_x2(bh, BhB + boff + (15 << 10));
                ldsm_x2(bl, BlB + boff + (15 << 10));
                mma_f16(acc[15], ah, bh);
                mma_f16(acc[15], al, bh);
                mma_f16(acc[15], ah, bl);
            }
        }

        if (more) {
            convertA(xv, nbuf);       // xv LDG latency was hidden by MMAs
            CP_WAIT0();
            __syncthreads();
        }
    }

    // ---- epilogue (registers only). Thread owns rows (w*16+q, +8),
    //      cols 8j + 2*c0 + e, with c0 = L&3, q = L>>2. acc scaled by 2^18.
    const int c0 = L & 3;
    float zz0 = 0.f, zz1 = 0.f;
#pragma unroll
    for (int j = 0; j < 13; ++j) {
#pragma unroll
        for (int e = 0; e < 2; ++e) {
            int col = 8 * j + 2 * c0 + e;
            if (col < LDIM) {
                float b = bes[col];
                float z0 = fmaf(acc[j][e],     INVS, b);  zz0 += z0 * z0;
                float z1 = fmaf(acc[j][e + 2], INVS, b);  zz1 += z1 * z1;
            }
        }
    }
    float bd0 = 3.4e38f, bd1 = 3.4e38f;
    int   bk0 = NCODES,  bk1 = NCODES;
#pragma unroll
    for (int j = 13; j < NT; ++j) {                // dots: cols 104..124
#pragma unroll
        for (int e = 0; e < 2; ++e) {
            int k = 8 * (j - 13) + 2 * c0 + e;
            if (k < NCODES) {
                float ckv = cks[k];
                float s0 = fmaf(acc[j][e],     -2.f * INVS, ckv);
                float s1 = fmaf(acc[j][e + 2], -2.f * INVS, ckv);
                if (s0 < bd0) { bd0 = s0; bk0 = k; }
                if (s1 < bd1) { bd1 = s1; bk1 = k; }
            }
        }
    }
#pragma unroll
    for (int off = 1; off < 4; off <<= 1) {
        float od0 = __shfl_xor_sync(0xffffffffu, bd0, off);
        int   ok0 = __shfl_xor_sync(0xffffffffu, bk0, off);
        float od1 = __shfl_xor_sync(0xffffffffu, bd1, off);
        int   ok1 = __shfl_xor_sync(0xffffffffu, bk1, off);
        zz0 += __shfl_xor_sync(0xffffffffu, zz0, off);
        zz1 += __shfl_xor_sync(0xffffffffu, zz1, off);
        if (od0 < bd0 || (od0 == bd0 && ok0 < bk0)) { bd0 = od0; bk0 = ok0; }
        if (od1 < bd1 || (od1 == bd1 && ok1 < bk1)) { bd1 = od1; bk1 = ok1; }
    }
    __syncthreads();              // acc/ldsm done; barrier before sidx reuse
    if (c0 == 0) {
        int q  = L >> 2;
        int r0 = w * 16 + q, r1 = r0 + 8;
        sidx[r0] = bk0;  sidx[r1] = bk1;
        out_idx[row0 + r0] = (float)bk0;
        out_idx[row0 + r1] = (float)bk1;
        atomicAdd(sloss, (zz0 + bd0) + (zz1 + bd1));
    }
    __syncthreads();
    if (t == 0) atomicAdd(&g_loss, (double)*sloss);

    // ---- fused recon gather (table L2-resident; streaming stores)
#pragma unroll 4
    for (int r = 0; r < CTA_M; ++r) {
        int k = sidx[r];
        float4 v = *(const float4*)(g_recon + (size_t)k * IDIM + t * 4);
        stcs4(out_recon + (size_t)(row0 + r) * IDIM + t * 4, v);
    }
}

// ---------------------------------------------------------------------------
// K2: finalize loss
// ---------------------------------------------------------------------------
__global__ void vq_fin_kernel(float* __restrict__ out_loss, int M) {
    out_loss[0] = (float)(1.1 * g_loss / ((double)M * (double)LDIM));
}

extern "C" void kernel_launch(void* const* d_in, const int* in_sizes, int n_in,
                              void* d_out, int out_size) {
    const float* x        = (const float*)d_in[0];
    const float* W_enc    = (const float*)d_in[1];
    const float* b_enc    = (const float*)d_in[2];
    const float* codebook = (const float*)d_in[3];
    const float* W_dec    = (const float*)d_in[4];
    const float* b_dec    = (const float*)d_in[5];
    float* out = (float*)d_out;

    const int M = in_sizes[0] / IDIM;           // 65536
    float* out_recon = out;
    float* out_loss  = out + (size_t)M * IDIM;
    float* out_idx   = out_loss + 1;

    cudaFuncSetAttribute(vq_main_kernel,
                         cudaFuncAttributeMaxDynamicSharedMemorySize, SMEM_BYTES);

    vq_setup_kernel<<<(NPAD * IDIM) / 256, 256>>>(W_enc, b_enc, codebook, W_dec, b_dec);
    vq_main_kernel<<<M / CTA_M, 256, SMEM_BYTES>>>(x, b_enc, out_recon, out_idx);
    vq_fin_kernel<<<1, 1>>>(out_loss, M);
}